// round 1
// baseline (speedup 1.0000x reference)
#include <cuda_runtime.h>
#include <cuda_bf16.h>
#include <cstdint>

// Problem constants
#define BATCH 8
#define NNODE 2048
#define DIM   256           // IN_DIM == OUT_DIM == 256
#define MROWS (BATCH * NNODE)   // 16384

// -------------------- scratch (no allocations allowed) --------------------
__device__ float g_H[(size_t)MROWS * DIM];   // 16 MB: h = x@W^T + b
__device__ float g_s1[MROWS];                // h@a1 + att_b
__device__ float g_s2[MROWS];                // h@a2

// ============================================================================
// Kernel 1: fp32 tiled GEMM  H[m,d] = sum_k X[m,k]*W[d,k] + b[d]
// 128x128 tile, BK=16, 256 threads, 8x8 per thread.
// ============================================================================
#define BM 128
#define BN 128
#define BK 16

__global__ void __launch_bounds__(256, 2)
gemm_h_kernel(const float* __restrict__ X, const float* __restrict__ W,
              const float* __restrict__ bias)
{
    __shared__ float As[BK][BM];
    __shared__ float Bs[BK][BN];

    const int tid   = threadIdx.x;
    const int cta_m = blockIdx.x * BM;
    const int cta_n = blockIdx.y * BN;

    const int tx   = tid & 15;        // 0..15
    const int ty   = tid >> 4;        // 0..15
    const int row0 = ty * 8;
    const int col0 = tx * 8;

    float acc[8][8];
#pragma unroll
    for (int i = 0; i < 8; i++)
#pragma unroll
        for (int j = 0; j < 8; j++) acc[i][j] = 0.f;

    for (int k0 = 0; k0 < DIM; k0 += BK) {
        // Load A tile: 128 rows x 16 k  (512 float4 / 256 threads = 2 each)
#pragma unroll
        for (int i = 0; i < 2; i++) {
            int idx = tid + i * 256;
            int r   = idx >> 2;
            int c4  = (idx & 3) * 4;
            float4 v = *(const float4*)(X + (size_t)(cta_m + r) * DIM + k0 + c4);
            As[c4 + 0][r] = v.x; As[c4 + 1][r] = v.y;
            As[c4 + 2][r] = v.z; As[c4 + 3][r] = v.w;
        }
        // Load B tile: 128 "d" rows x 16 k
#pragma unroll
        for (int i = 0; i < 2; i++) {
            int idx = tid + i * 256;
            int r   = idx >> 2;
            int c4  = (idx & 3) * 4;
            float4 v = *(const float4*)(W + (size_t)(cta_n + r) * DIM + k0 + c4);
            Bs[c4 + 0][r] = v.x; Bs[c4 + 1][r] = v.y;
            Bs[c4 + 2][r] = v.z; Bs[c4 + 3][r] = v.w;
        }
        __syncthreads();

#pragma unroll
        for (int kk = 0; kk < BK; kk++) {
            float a[8], bb[8];
            *(float4*)&a[0]  = *(const float4*)&As[kk][row0];
            *(float4*)&a[4]  = *(const float4*)&As[kk][row0 + 4];
            *(float4*)&bb[0] = *(const float4*)&Bs[kk][col0];
            *(float4*)&bb[4] = *(const float4*)&Bs[kk][col0 + 4];
#pragma unroll
            for (int i = 0; i < 8; i++)
#pragma unroll
                for (int j = 0; j < 8; j++)
                    acc[i][j] += a[i] * bb[j];
        }
        __syncthreads();
    }

    // Epilogue: + bias, write H
    float bv[8];
    *(float4*)&bv[0] = *(const float4*)(bias + cta_n + col0);
    *(float4*)&bv[4] = *(const float4*)(bias + cta_n + col0 + 4);

#pragma unroll
    for (int i = 0; i < 8; i++) {
        float* hp = g_H + (size_t)(cta_m + row0 + i) * DIM + cta_n + col0;
        float4 v0 = make_float4(acc[i][0] + bv[0], acc[i][1] + bv[1],
                                acc[i][2] + bv[2], acc[i][3] + bv[3]);
        float4 v1 = make_float4(acc[i][4] + bv[4], acc[i][5] + bv[5],
                                acc[i][6] + bv[6], acc[i][7] + bv[7]);
        *(float4*)(hp)     = v0;
        *(float4*)(hp + 4) = v1;
    }
}

// ============================================================================
// Kernel 2: s1[r] = h[r,:]@a1 + att_b ; s2[r] = h[r,:]@a2
// One warp per row, 8 rows per 256-thread block.
// ============================================================================
__global__ void __launch_bounds__(256)
sproj_kernel(const float* __restrict__ a1, const float* __restrict__ a2,
             const float* __restrict__ att_b)
{
    const int row  = blockIdx.x * 8 + (threadIdx.x >> 5);
    const int lane = threadIdx.x & 31;
    const float* hr = g_H + (size_t)row * DIM;

    float d1 = 0.f, d2 = 0.f;
#pragma unroll
    for (int k = lane; k < DIM; k += 32) {
        float hv = hr[k];
        d1 += hv * __ldg(a1 + k);
        d2 += hv * __ldg(a2 + k);
    }
#pragma unroll
    for (int o = 16; o; o >>= 1) {
        d1 += __shfl_xor_sync(0xffffffffu, d1, o);
        d2 += __shfl_xor_sync(0xffffffffu, d2, o);
    }
    if (lane == 0) {
        g_s1[row] = d1 + att_b[0];
        g_s2[row] = d2;
    }
}

// ============================================================================
// Kernel 3: per-node attention + sparse aggregation.
// CTA = (i, b), 256 threads (one per output channel d).
//   Phase A: scan adj row, compute w = sigmoid(s1_i+s2_j)*adj*mask_j,
//            warp-ballot compact nonzeros into smem (w,j) list, row-sum.
//   Phase B: acc_d = sum_k w_k * H[j_k, d]; out = acc / (sum+1e-8) (mask_i==1).
// ============================================================================
__global__ void __launch_bounds__(256)
attn_agg_kernel(const float* __restrict__ adj, const float* __restrict__ mask,
                float* __restrict__ out)
{
    const int i   = blockIdx.x;
    const int b   = blockIdx.y;
    const int tid = threadIdx.x;
    const int row = b * NNODE + i;

    __shared__ float wbuf[NNODE];
    __shared__ int   jbuf[NNODE];
    __shared__ int   s_cnt;
    __shared__ float s_sum;

    const float mi = mask[row];
    float* orow = out + (size_t)row * DIM;
    if (mi == 0.f) {                 // uniform across block
        orow[tid] = 0.f;
        return;
    }

    if (tid == 0) { s_cnt = 0; s_sum = 0.f; }
    __syncthreads();

    const float* arow = adj + (size_t)row * NNODE;
    const float  s1i  = g_s1[row];
    const float* mrow = mask + b * NNODE;
    const float* s2b  = g_s2 + b * NNODE;

    const int lane = tid & 31;
    float psum = 0.f;

#pragma unroll
    for (int k = 0; k < NNODE / 256; k++) {
        int j = tid + k * 256;
        float av = arow[j];
        float mj = mrow[j];
        float w  = 0.f;
        if (av != 0.f && mj != 0.f) {
            float lg = s1i + s2b[j];
            w = av * mj / (1.f + __expf(-lg));
        }
        psum += w;
        unsigned bal = __ballot_sync(0xffffffffu, w != 0.f);
        if (bal) {
            int leader = __ffs(bal) - 1;
            int base = 0;
            if (lane == leader) base = atomicAdd(&s_cnt, __popc(bal));
            base = __shfl_sync(0xffffffffu, base, leader);
            if (w != 0.f) {
                int rank = __popc(bal & ((1u << lane) - 1u));
                wbuf[base + rank] = w;
                jbuf[base + rank] = j;
            }
        }
    }
    // block-reduce row sum
#pragma unroll
    for (int o = 16; o; o >>= 1) psum += __shfl_xor_sync(0xffffffffu, psum, o);
    if (lane == 0) atomicAdd(&s_sum, psum);
    __syncthreads();

    const int n = s_cnt;
    const float* Hb = g_H + (size_t)b * NNODE * DIM;

    float acc = 0.f;
    int k = 0;
    for (; k + 4 <= n; k += 4) {
        int   j0 = jbuf[k],     j1 = jbuf[k + 1], j2 = jbuf[k + 2], j3 = jbuf[k + 3];
        float w0 = wbuf[k],     w1 = wbuf[k + 1], w2 = wbuf[k + 2], w3 = wbuf[k + 3];
        float h0 = Hb[(size_t)j0 * DIM + tid];
        float h1 = Hb[(size_t)j1 * DIM + tid];
        float h2 = Hb[(size_t)j2 * DIM + tid];
        float h3 = Hb[(size_t)j3 * DIM + tid];
        acc += w0 * h0; acc += w1 * h1; acc += w2 * h2; acc += w3 * h3;
    }
    for (; k < n; k++)
        acc += wbuf[k] * Hb[(size_t)jbuf[k] * DIM + tid];

    const float inv = 1.f / (s_sum + 1e-8f);
    orow[tid] = acc * inv;
}

// ============================================================================
// Launch
// ============================================================================
extern "C" void kernel_launch(void* const* d_in, const int* in_sizes, int n_in,
                              void* d_out, int out_size)
{
    const float* x     = (const float*)d_in[0];
    const float* adj   = (const float*)d_in[1];
    const float* mask  = (const float*)d_in[2];
    const float* W     = (const float*)d_in[3];
    const float* bias  = (const float*)d_in[4];
    const float* a1    = (const float*)d_in[5];
    const float* a2    = (const float*)d_in[6];
    const float* att_b = (const float*)d_in[7];
    float* out = (float*)d_out;

    dim3 g1(MROWS / BM, DIM / BN);        // (128, 2)
    gemm_h_kernel<<<g1, 256>>>(x, W, bias);

    sproj_kernel<<<MROWS / 8, 256>>>(a1, a2, att_b);

    dim3 g3(NNODE, BATCH);                // (2048, 8)
    attn_agg_kernel<<<g3, 256>>>(adj, mask, out);
}

// round 2
// speedup vs baseline: 1.2614x; 1.2614x over previous
#include <cuda_runtime.h>
#include <cuda_bf16.h>
#include <cstdint>

// Problem constants
#define BATCH 8
#define NNODE 2048
#define DIM   256           // IN_DIM == OUT_DIM == 256
#define MROWS (BATCH * NNODE)   // 16384

// -------------------- scratch (no allocations allowed) --------------------
__device__ float g_H[(size_t)MROWS * DIM];   // 16 MB: h = x@W^T + b
__device__ float g_s1[MROWS];                // h@a1 + att_b
__device__ float g_s2[MROWS];                // h@a2

// ============================================================================
// Kernel 1: fp32 tiled GEMM  H[m,d] = sum_k X[m,k]*W[d,k] + b[d]
// 128x128 tile, BK=8, 256 threads, 8x8 per thread.
// Double-buffered smem + packed fma.rn.f32x2 inner loop (2x fp32 throughput).
// ============================================================================
#define BM 128
#define BN 128
#define BK 8

__global__ void __launch_bounds__(256, 2)
gemm_h_kernel(const float* __restrict__ X, const float* __restrict__ W,
              const float* __restrict__ bias)
{
    __shared__ float As[2][BK][BM];   // 2 * 4 KB
    __shared__ float Bs[2][BK][BN];   // 2 * 4 KB

    const int tid   = threadIdx.x;
    const int cta_m = blockIdx.x * BM;
    const int cta_n = blockIdx.y * BN;

    const int tx   = tid & 15;        // 0..15
    const int ty   = tid >> 4;        // 0..15
    const int row0 = ty * 8;
    const int col0 = tx * 8;

    // global loaders: thread -> (row = tid>>1, k-quad = (tid&1)*4)
    const int lr = tid >> 1;          // 0..127
    const int lc = (tid & 1) * 4;     // 0 or 4

    const float* Xp = X + (size_t)(cta_m + lr) * DIM + lc;
    const float* Wp = W + (size_t)(cta_n + lr) * DIM + lc;

    // prologue: tile 0 -> buffer 0
    {
        float4 a = *(const float4*)(Xp);
        float4 b = *(const float4*)(Wp);
        As[0][lc + 0][lr] = a.x; As[0][lc + 1][lr] = a.y;
        As[0][lc + 2][lr] = a.z; As[0][lc + 3][lr] = a.w;
        Bs[0][lc + 0][lr] = b.x; Bs[0][lc + 1][lr] = b.y;
        Bs[0][lc + 2][lr] = b.z; Bs[0][lc + 3][lr] = b.w;
    }
    __syncthreads();

    // packed accumulators: accp[i][j] holds (acc[i][2j], acc[i][2j+1])
    unsigned long long accp[8][4];
#pragma unroll
    for (int i = 0; i < 8; i++)
#pragma unroll
        for (int j = 0; j < 4; j++) accp[i][j] = 0ull;

    int buf = 0;
    for (int k0 = 0; k0 < DIM; k0 += BK) {
        const bool has_next = (k0 + BK) < DIM;
        float4 na, nb;
        if (has_next) {
            na = *(const float4*)(Xp + k0 + BK);
            nb = *(const float4*)(Wp + k0 + BK);
        }

#pragma unroll
        for (int kk = 0; kk < BK; kk++) {
            float a8[8];
            *(float4*)&a8[0] = *(const float4*)&As[buf][kk][row0];
            *(float4*)&a8[4] = *(const float4*)&As[buf][kk][row0 + 4];
            ulonglong2 bb0 = *(const ulonglong2*)&Bs[buf][kk][col0];
            ulonglong2 bb1 = *(const ulonglong2*)&Bs[buf][kk][col0 + 4];
            unsigned long long b2[4] = {bb0.x, bb0.y, bb1.x, bb1.y};

            unsigned long long a2[8];
#pragma unroll
            for (int i = 0; i < 8; i++)
                asm("mov.b64 %0, {%1, %1};" : "=l"(a2[i]) : "f"(a8[i]));

#pragma unroll
            for (int i = 0; i < 8; i++)
#pragma unroll
                for (int j = 0; j < 4; j++)
                    asm("fma.rn.f32x2 %0, %1, %2, %0;"
                        : "+l"(accp[i][j]) : "l"(a2[i]), "l"(b2[j]));
        }

        if (has_next) {
            As[buf ^ 1][lc + 0][lr] = na.x; As[buf ^ 1][lc + 1][lr] = na.y;
            As[buf ^ 1][lc + 2][lr] = na.z; As[buf ^ 1][lc + 3][lr] = na.w;
            Bs[buf ^ 1][lc + 0][lr] = nb.x; Bs[buf ^ 1][lc + 1][lr] = nb.y;
            Bs[buf ^ 1][lc + 2][lr] = nb.z; Bs[buf ^ 1][lc + 3][lr] = nb.w;
            __syncthreads();
            buf ^= 1;
        }
    }

    // Epilogue: + bias, write H
    float bv[8];
    *(float4*)&bv[0] = *(const float4*)(bias + cta_n + col0);
    *(float4*)&bv[4] = *(const float4*)(bias + cta_n + col0 + 4);

#pragma unroll
    for (int i = 0; i < 8; i++) {
        const float* af = (const float*)&accp[i][0];   // 8 floats, in order
        float* hp = g_H + (size_t)(cta_m + row0 + i) * DIM + cta_n + col0;
        float4 v0 = make_float4(af[0] + bv[0], af[1] + bv[1],
                                af[2] + bv[2], af[3] + bv[3]);
        float4 v1 = make_float4(af[4] + bv[4], af[5] + bv[5],
                                af[6] + bv[6], af[7] + bv[7]);
        *(float4*)(hp)     = v0;
        *(float4*)(hp + 4) = v1;
    }
}

// ============================================================================
// Kernel 2: s1[r] = h[r,:]@a1 + att_b ; s2[r] = h[r,:]@a2
// One warp per row, 8 rows per 256-thread block.
// ============================================================================
__global__ void __launch_bounds__(256)
sproj_kernel(const float* __restrict__ a1, const float* __restrict__ a2,
             const float* __restrict__ att_b)
{
    const int row  = blockIdx.x * 8 + (threadIdx.x >> 5);
    const int lane = threadIdx.x & 31;
    const float* hr = g_H + (size_t)row * DIM;

    float d1 = 0.f, d2 = 0.f;
#pragma unroll
    for (int k = lane; k < DIM; k += 32) {
        float hv = hr[k];
        d1 += hv * __ldg(a1 + k);
        d2 += hv * __ldg(a2 + k);
    }
#pragma unroll
    for (int o = 16; o; o >>= 1) {
        d1 += __shfl_xor_sync(0xffffffffu, d1, o);
        d2 += __shfl_xor_sync(0xffffffffu, d2, o);
    }
    if (lane == 0) {
        g_s1[row] = d1 + att_b[0];
        g_s2[row] = d2;
    }
}

// ============================================================================
// Kernel 3: per-node attention + sparse aggregation.
// CTA = (i, b), 256 threads.
//   Phase A: float4-batched scan of adj row (full MLP before any ballot),
//            w = sigmoid(s1_i+s2_j)*adj*mask_j, warp-ballot compaction.
//   Phase B: 4 neighbor-groups x 64 channel-quads; float4 gathers, unroll-2,
//            cross-group smem reduction. out = acc / (sum+1e-8).
// ============================================================================
__global__ void __launch_bounds__(256)
attn_agg_kernel(const float* __restrict__ adj, const float* __restrict__ mask,
                float* __restrict__ out)
{
    const int i   = blockIdx.x;
    const int b   = blockIdx.y;
    const int tid = threadIdx.x;
    const int row = b * NNODE + i;

    __shared__ float wbuf[NNODE];        // 8 KB
    __shared__ int   jbuf[NNODE];        // 8 KB
    __shared__ float sred[4][DIM];       // 4 KB
    __shared__ int   s_cnt;
    __shared__ float s_sum;

    const float mi = mask[row];
    float* orow = out + (size_t)row * DIM;
    if (mi == 0.f) {                     // uniform across block
        orow[tid] = 0.f;
        return;
    }

    if (tid == 0) { s_cnt = 0; s_sum = 0.f; }
    __syncthreads();

    const float* arow = adj + (size_t)row * NNODE;
    const float  s1i  = g_s1[row];
    const float* mrow = mask + b * NNODE;
    const float* s2b  = g_s2 + b * NNODE;
    const int lane = tid & 31;

    // ---- Phase A: batched loads (all independent, MLP-high), then compact ----
    float4 av[2], mv[2], sv[2];
#pragma unroll
    for (int u = 0; u < 2; u++) {
        int j0 = tid * 4 + u * 1024;
        av[u] = *(const float4*)(arow + j0);
        mv[u] = *(const float4*)(mrow + j0);
        sv[u] = *(const float4*)(s2b + j0);
    }

    float w[8];
    float psum = 0.f;
#pragma unroll
    for (int u = 0; u < 2; u++) {
        const float* ap = (const float*)&av[u];
        const float* mp = (const float*)&mv[u];
        const float* sp = (const float*)&sv[u];
#pragma unroll
        for (int e = 0; e < 4; e++) {
            float ww = 0.f;
            if (ap[e] != 0.f && mp[e] != 0.f) {
                float lg = s1i + sp[e];
                ww = ap[e] * mp[e] / (1.f + __expf(-lg));
            }
            w[u * 4 + e] = ww;
            psum += ww;
        }
    }

#pragma unroll
    for (int e = 0; e < 8; e++) {
        unsigned bal = __ballot_sync(0xffffffffu, w[e] != 0.f);
        if (bal) {
            int leader = __ffs(bal) - 1;
            int base = 0;
            if (lane == leader) base = atomicAdd(&s_cnt, __popc(bal));
            base = __shfl_sync(0xffffffffu, base, leader);
            if (w[e] != 0.f) {
                int rank = __popc(bal & ((1u << lane) - 1u));
                wbuf[base + rank] = w[e];
                jbuf[base + rank] = tid * 4 + (e >> 2) * 1024 + (e & 3);
            }
        }
    }

#pragma unroll
    for (int o = 16; o; o >>= 1) psum += __shfl_xor_sync(0xffffffffu, psum, o);
    if (lane == 0) atomicAdd(&s_sum, psum);
    __syncthreads();

    // ---- Phase B: grouped float4 gather ----
    const int n   = s_cnt;
    const float inv = 1.f / (s_sum + 1e-8f);
    const float* Hb = g_H + (size_t)b * NNODE * DIM;

    const int g  = tid >> 6;             // neighbor group 0..3
    const int c4 = (tid & 63) * 4;       // channel quad

    float4 acc = make_float4(0.f, 0.f, 0.f, 0.f);
    int k = g;
    for (; k + 4 < n; k += 8) {          // two neighbors per iter (k, k+4)
        int   ja = jbuf[k],   jc = jbuf[k + 4];
        float wa = wbuf[k],   wc = wbuf[k + 4];
        float4 ha = *(const float4*)(Hb + (size_t)ja * DIM + c4);
        float4 hc = *(const float4*)(Hb + (size_t)jc * DIM + c4);
        acc.x += wa * ha.x + wc * hc.x;
        acc.y += wa * ha.y + wc * hc.y;
        acc.z += wa * ha.z + wc * hc.z;
        acc.w += wa * ha.w + wc * hc.w;
    }
    if (k < n) {
        int   ja = jbuf[k];
        float wa = wbuf[k];
        float4 ha = *(const float4*)(Hb + (size_t)ja * DIM + c4);
        acc.x += wa * ha.x; acc.y += wa * ha.y;
        acc.z += wa * ha.z; acc.w += wa * ha.w;
    }

    *(float4*)&sred[g][c4] = acc;
    __syncthreads();

    float r = sred[0][tid] + sred[1][tid] + sred[2][tid] + sred[3][tid];
    orow[tid] = r * inv;
}

// ============================================================================
// Launch
// ============================================================================
extern "C" void kernel_launch(void* const* d_in, const int* in_sizes, int n_in,
                              void* d_out, int out_size)
{
    const float* x     = (const float*)d_in[0];
    const float* adj   = (const float*)d_in[1];
    const float* mask  = (const float*)d_in[2];
    const float* W     = (const float*)d_in[3];
    const float* bias  = (const float*)d_in[4];
    const float* a1    = (const float*)d_in[5];
    const float* a2    = (const float*)d_in[6];
    const float* att_b = (const float*)d_in[7];
    float* out = (float*)d_out;

    dim3 g1(MROWS / BM, DIM / BN);        // (128, 2)
    gemm_h_kernel<<<g1, 256>>>(x, W, bias);

    sproj_kernel<<<MROWS / 8, 256>>>(a1, a2, att_b);

    dim3 g3(NNODE, BATCH);                // (2048, 8)
    attn_agg_kernel<<<g3, 256>>>(adj, mask, out);
}

// round 5
// speedup vs baseline: 1.3746x; 1.0898x over previous
#include <cuda_runtime.h>
#include <cuda_bf16.h>
#include <cstdint>

// Problem constants
#define BATCH 8
#define NNODE 2048
#define DIM   256
#define MROWS (BATCH * NNODE)   // 16384

// -------------------- scratch (no allocations allowed) --------------------
__device__ float g_H[(size_t)MROWS * DIM];   // 16 MB: h = x@W^T + b
__device__ float g_s1[MROWS];
__device__ float g_s2[MROWS];

// ============================================================================
// Helpers (base sm_103 target: ldmatrix + mma.sync only, NO tcgen05)
// ============================================================================
__device__ __forceinline__ uint32_t smem_u32(const void* p) {
    uint32_t a;
    asm("{ .reg .u64 t; cvta.to.shared.u64 t, %1; cvt.u32.u64 %0, t; }"
        : "=r"(a) : "l"(p));
    return a;
}

__device__ __forceinline__ void ldm_x4(uint32_t* r, uint32_t addr) {
    asm volatile("ldmatrix.sync.aligned.m8n8.x4.shared.b16 {%0,%1,%2,%3}, [%4];"
        : "=r"(r[0]), "=r"(r[1]), "=r"(r[2]), "=r"(r[3]) : "r"(addr));
}

__device__ __forceinline__ void mma_bf16(float* c, const uint32_t* a,
                                         const uint32_t* b) {
    asm volatile(
        "mma.sync.aligned.m16n8k16.row.col.f32.bf16.bf16.f32 "
        "{%0,%1,%2,%3}, {%4,%5,%6,%7}, {%8,%9}, {%0,%1,%2,%3};"
        : "+f"(c[0]), "+f"(c[1]), "+f"(c[2]), "+f"(c[3])
        : "r"(a[0]), "r"(a[1]), "r"(a[2]), "r"(a[3]), "r"(b[0]), "r"(b[1]));
}

// bf16 split: hi = bf16(x), lo = bf16(x - hi); packs (e0, e1) pairs.
__device__ __forceinline__ void split_pair(float e0, float e1,
                                           uint32_t& h, uint32_t& l) {
    asm("cvt.rn.bf16x2.f32 %0, %1, %2;" : "=r"(h) : "f"(e1), "f"(e0));
    __nv_bfloat162 hb = *(__nv_bfloat162*)&h;
    float r0 = e0 - __bfloat162float(hb.x);
    float r1 = e1 - __bfloat162float(hb.y);
    asm("cvt.rn.bf16x2.f32 %0, %1, %2;" : "=r"(l) : "f"(r1), "f"(r0));
}

// ============================================================================
// Kernel 1: split-bf16 HMMA GEMM  H[m,d] = sum_k X[m,k]*W[d,k] + b[d]
// CTA 128x128, 8 warps (2x4), warp tile 64x32, K-step 16, single-buffer smem.
// D = Ahi*Bhi + Ahi*Blo + Alo*Bhi (fp32 accumulate).
// ============================================================================
#define SROW 24   // smem row stride in bf16 elements (48 B, conflict-free ldmatrix)

__global__ void __launch_bounds__(256, 1)
gemm_h_mma(const float* __restrict__ X, const float* __restrict__ W,
           const float* __restrict__ bias)
{
    __shared__ __nv_bfloat16 sAhi[128][SROW];   // 6 KB each
    __shared__ __nv_bfloat16 sAlo[128][SROW];
    __shared__ __nv_bfloat16 sBhi[128][SROW];
    __shared__ __nv_bfloat16 sBlo[128][SROW];

    const int tid   = threadIdx.x;
    const int wid   = tid >> 5;
    const int lane  = tid & 31;
    const int cta_m = blockIdx.x * 128;
    const int cta_n = blockIdx.y * 128;

    const int wm = (wid & 1) * 64;    // warp M offset within CTA
    const int wn = (wid >> 1) * 32;   // warp N offset within CTA

    // Loader mapping: thread -> (row = tid>>1, 8 consecutive k at lq*4)
    const int lr = tid >> 1;
    const int lq = (tid & 1) * 2;                 // quad index 0 or 2
    const float* Xrow = X + (size_t)(cta_m + lr) * DIM;
    const float* Wrow = W + (size_t)(cta_n + lr) * DIM;
    uint32_t* pAhi = (uint32_t*)sAhi[lr];
    uint32_t* pAlo = (uint32_t*)sAlo[lr];
    uint32_t* pBhi = (uint32_t*)sBhi[lr];
    uint32_t* pBlo = (uint32_t*)sBlo[lr];

    // ldmatrix addresses (constant across k-steps; single buffer)
    uint32_t aAhi[4], aAlo[4];                    // per m16 tile
#pragma unroll
    for (int mt = 0; mt < 4; mt++) {
        int row = wm + mt * 16 + (lane & 15);
        int kh  = (lane >> 4) * 8;
        aAhi[mt] = smem_u32(&sAhi[row][kh]);
        aAlo[mt] = smem_u32(&sAlo[row][kh]);
    }
    uint32_t bBhi[2], bBlo[2];                    // per pair of n8 tiles
#pragma unroll
    for (int nt2 = 0; nt2 < 2; nt2++) {
        int nr = wn + nt2 * 16 + ((lane >> 4) * 8) + (lane & 7);
        int kh = ((lane >> 3) & 1) * 8;
        bBhi[nt2] = smem_u32(&sBhi[nr][kh]);
        bBlo[nt2] = smem_u32(&sBlo[nr][kh]);
    }

    float acc[4][4][4];                           // [mt][nt][c0..c3]
#pragma unroll
    for (int mt = 0; mt < 4; mt++)
#pragma unroll
        for (int nt = 0; nt < 4; nt++)
#pragma unroll
            for (int c = 0; c < 4; c++) acc[mt][nt][c] = 0.f;

#pragma unroll 1
    for (int ks = 0; ks < DIM / 16; ks++) {
        const int k0 = ks * 16;

        // ---- load + split-convert A and B tiles into smem ----
        {
            float4 xa = *(const float4*)(Xrow + k0 + lq * 4);
            float4 xb = *(const float4*)(Xrow + k0 + lq * 4 + 4);
            float4 wa = *(const float4*)(Wrow + k0 + lq * 4);
            float4 wb = *(const float4*)(Wrow + k0 + lq * 4 + 4);
            uint32_t h, l;
            split_pair(xa.x, xa.y, h, l); pAhi[lq * 2 + 0] = h; pAlo[lq * 2 + 0] = l;
            split_pair(xa.z, xa.w, h, l); pAhi[lq * 2 + 1] = h; pAlo[lq * 2 + 1] = l;
            split_pair(xb.x, xb.y, h, l); pAhi[lq * 2 + 2] = h; pAlo[lq * 2 + 2] = l;
            split_pair(xb.z, xb.w, h, l); pAhi[lq * 2 + 3] = h; pAlo[lq * 2 + 3] = l;
            split_pair(wa.x, wa.y, h, l); pBhi[lq * 2 + 0] = h; pBlo[lq * 2 + 0] = l;
            split_pair(wa.z, wa.w, h, l); pBhi[lq * 2 + 1] = h; pBlo[lq * 2 + 1] = l;
            split_pair(wb.x, wb.y, h, l); pBhi[lq * 2 + 2] = h; pBlo[lq * 2 + 2] = l;
            split_pair(wb.z, wb.w, h, l); pBhi[lq * 2 + 3] = h; pBlo[lq * 2 + 3] = l;
        }
        __syncthreads();

        // ---- fragments ----
        uint32_t fAhi[4][4], fAlo[4][4];
#pragma unroll
        for (int mt = 0; mt < 4; mt++) {
            ldm_x4(fAhi[mt], aAhi[mt]);
            ldm_x4(fAlo[mt], aAlo[mt]);
        }
        uint32_t fBhi[4][2], fBlo[4][2];
#pragma unroll
        for (int nt2 = 0; nt2 < 2; nt2++) {
            uint32_t r[4];
            ldm_x4(r, bBhi[nt2]);
            fBhi[nt2 * 2][0] = r[0]; fBhi[nt2 * 2][1] = r[1];
            fBhi[nt2 * 2 + 1][0] = r[2]; fBhi[nt2 * 2 + 1][1] = r[3];
            ldm_x4(r, bBlo[nt2]);
            fBlo[nt2 * 2][0] = r[0]; fBlo[nt2 * 2][1] = r[1];
            fBlo[nt2 * 2 + 1][0] = r[2]; fBlo[nt2 * 2 + 1][1] = r[3];
        }

        // ---- 3-product MMA ----
#pragma unroll
        for (int mt = 0; mt < 4; mt++)
#pragma unroll
            for (int nt = 0; nt < 4; nt++) {
                mma_bf16(acc[mt][nt], fAhi[mt], fBhi[nt]);
                mma_bf16(acc[mt][nt], fAhi[mt], fBlo[nt]);
                mma_bf16(acc[mt][nt], fAlo[mt], fBhi[nt]);
            }
        __syncthreads();
    }

    // ---- epilogue: +bias, store H ----
    const int gid = lane >> 2;          // 0..7
    const int tig = lane & 3;           // 0..3
#pragma unroll
    for (int nt = 0; nt < 4; nt++) {
        const int col = cta_n + wn + nt * 8 + tig * 2;
        const float2 bv = *(const float2*)(bias + col);
#pragma unroll
        for (int mt = 0; mt < 4; mt++) {
            const int m0 = cta_m + wm + mt * 16 + gid;
            float2 v0 = make_float2(acc[mt][nt][0] + bv.x, acc[mt][nt][1] + bv.y);
            float2 v1 = make_float2(acc[mt][nt][2] + bv.x, acc[mt][nt][3] + bv.y);
            *(float2*)(g_H + (size_t)m0 * DIM + col)       = v0;
            *(float2*)(g_H + (size_t)(m0 + 8) * DIM + col) = v1;
        }
    }
}

// ============================================================================
// Kernel 2: s1[r] = h[r,:]@a1 + att_b ; s2[r] = h[r,:]@a2
// ============================================================================
__global__ void __launch_bounds__(256)
sproj_kernel(const float* __restrict__ a1, const float* __restrict__ a2,
             const float* __restrict__ att_b)
{
    const int row  = blockIdx.x * 8 + (threadIdx.x >> 5);
    const int lane = threadIdx.x & 31;
    const float* hr = g_H + (size_t)row * DIM;

    float d1 = 0.f, d2 = 0.f;
#pragma unroll
    for (int k = lane; k < DIM; k += 32) {
        float hv = hr[k];
        d1 += hv * __ldg(a1 + k);
        d2 += hv * __ldg(a2 + k);
    }
#pragma unroll
    for (int o = 16; o; o >>= 1) {
        d1 += __shfl_xor_sync(0xffffffffu, d1, o);
        d2 += __shfl_xor_sync(0xffffffffu, d2, o);
    }
    if (lane == 0) {
        g_s1[row] = d1 + att_b[0];
        g_s2[row] = d2;
    }
}

// ============================================================================
// Kernel 3: per-node attention + sparse aggregation (R2 version, passing).
// ============================================================================
__global__ void __launch_bounds__(256)
attn_agg_kernel(const float* __restrict__ adj, const float* __restrict__ mask,
                float* __restrict__ out)
{
    const int i   = blockIdx.x;
    const int b   = blockIdx.y;
    const int tid = threadIdx.x;
    const int row = b * NNODE + i;

    __shared__ float wbuf[NNODE];
    __shared__ int   jbuf[NNODE];
    __shared__ float sred[4][DIM];
    __shared__ int   s_cnt;
    __shared__ float s_sum;

    const float mi = mask[row];
    float* orow = out + (size_t)row * DIM;
    if (mi == 0.f) {
        orow[tid] = 0.f;
        return;
    }

    if (tid == 0) { s_cnt = 0; s_sum = 0.f; }
    __syncthreads();

    const float* arow = adj + (size_t)row * NNODE;
    const float  s1i  = g_s1[row];
    const float* mrow = mask + b * NNODE;
    const float* s2b  = g_s2 + b * NNODE;
    const int lane = tid & 31;

    float4 av[2], mv[2], sv[2];
#pragma unroll
    for (int u = 0; u < 2; u++) {
        int j0 = tid * 4 + u * 1024;
        av[u] = *(const float4*)(arow + j0);
        mv[u] = *(const float4*)(mrow + j0);
        sv[u] = *(const float4*)(s2b + j0);
    }

    float w[8];
    float psum = 0.f;
#pragma unroll
    for (int u = 0; u < 2; u++) {
        const float* ap = (const float*)&av[u];
        const float* mp = (const float*)&mv[u];
        const float* sp = (const float*)&sv[u];
#pragma unroll
        for (int e = 0; e < 4; e++) {
            float ww = 0.f;
            if (ap[e] != 0.f && mp[e] != 0.f) {
                float lg = s1i + sp[e];
                ww = ap[e] * mp[e] / (1.f + __expf(-lg));
            }
            w[u * 4 + e] = ww;
            psum += ww;
        }
    }

#pragma unroll
    for (int e = 0; e < 8; e++) {
        unsigned bal = __ballot_sync(0xffffffffu, w[e] != 0.f);
        if (bal) {
            int leader = __ffs(bal) - 1;
            int base = 0;
            if (lane == leader) base = atomicAdd(&s_cnt, __popc(bal));
            base = __shfl_sync(0xffffffffu, base, leader);
            if (w[e] != 0.f) {
                int rank = __popc(bal & ((1u << lane) - 1u));
                wbuf[base + rank] = w[e];
                jbuf[base + rank] = tid * 4 + (e >> 2) * 1024 + (e & 3);
            }
        }
    }

#pragma unroll
    for (int o = 16; o; o >>= 1) psum += __shfl_xor_sync(0xffffffffu, psum, o);
    if (lane == 0) atomicAdd(&s_sum, psum);
    __syncthreads();

    const int n   = s_cnt;
    const float inv = 1.f / (s_sum + 1e-8f);
    const float* Hb = g_H + (size_t)b * NNODE * DIM;

    const int g  = tid >> 6;
    const int c4 = (tid & 63) * 4;

    float4 acc = make_float4(0.f, 0.f, 0.f, 0.f);
    int k = g;
    for (; k + 4 < n; k += 8) {
        int   ja = jbuf[k],   jc = jbuf[k + 4];
        float wa = wbuf[k],   wc = wbuf[k + 4];
        float4 ha = *(const float4*)(Hb + (size_t)ja * DIM + c4);
        float4 hc = *(const float4*)(Hb + (size_t)jc * DIM + c4);
        acc.x += wa * ha.x + wc * hc.x;
        acc.y += wa * ha.y + wc * hc.y;
        acc.z += wa * ha.z + wc * hc.z;
        acc.w += wa * ha.w + wc * hc.w;
    }
    if (k < n) {
        int   ja = jbuf[k];
        float wa = wbuf[k];
        float4 ha = *(const float4*)(Hb + (size_t)ja * DIM + c4);
        acc.x += wa * ha.x; acc.y += wa * ha.y;
        acc.z += wa * ha.z; acc.w += wa * ha.w;
    }

    *(float4*)&sred[g][c4] = acc;
    __syncthreads();

    float r = sred[0][tid] + sred[1][tid] + sred[2][tid] + sred[3][tid];
    orow[tid] = r * inv;
}

// ============================================================================
// Launch
// ============================================================================
extern "C" void kernel_launch(void* const* d_in, const int* in_sizes, int n_in,
                              void* d_out, int out_size)
{
    const float* x     = (const float*)d_in[0];
    const float* adj   = (const float*)d_in[1];
    const float* mask  = (const float*)d_in[2];
    const float* W     = (const float*)d_in[3];
    const float* bias  = (const float*)d_in[4];
    const float* a1    = (const float*)d_in[5];
    const float* a2    = (const float*)d_in[6];
    const float* att_b = (const float*)d_in[7];
    float* out = (float*)d_out;

    dim3 g1(MROWS / 128, DIM / 128);      // (128, 2)
    gemm_h_mma<<<g1, 256>>>(x, W, bias);

    sproj_kernel<<<MROWS / 8, 256>>>(a1, a2, att_b);

    dim3 g3(NNODE, BATCH);                // (2048, 8)
    attn_agg_kernel<<<g3, 256>>>(adj, mask, out);
}

// round 6
// speedup vs baseline: 1.4639x; 1.0650x over previous
#include <cuda_runtime.h>
#include <cuda_bf16.h>
#include <cstdint>

// Problem constants
#define BATCH 8
#define NNODE 2048
#define DIM   256
#define MROWS (BATCH * NNODE)   // 16384

// -------------------- scratch (no allocations allowed) --------------------
__device__ float g_H[(size_t)MROWS * DIM];   // 16 MB
__device__ float g_s1[MROWS];
__device__ float g_s2[MROWS];
__device__ __nv_bfloat16 g_Xhi[(size_t)MROWS * DIM];   // 8 MB
__device__ __nv_bfloat16 g_Xlo[(size_t)MROWS * DIM];   // 8 MB
__device__ __nv_bfloat16 g_Whi[DIM * DIM];
__device__ __nv_bfloat16 g_Wlo[DIM * DIM];

// ============================================================================
// Helpers (base sm_103 target: ldmatrix + mma.sync + cp.async; NO tcgen05)
// ============================================================================
__device__ __forceinline__ uint32_t smem_u32(const void* p) {
    uint32_t a;
    asm("{ .reg .u64 t; cvta.to.shared.u64 t, %1; cvt.u32.u64 %0, t; }"
        : "=r"(a) : "l"(p));
    return a;
}

__device__ __forceinline__ void cp16(uint32_t dst, const void* src) {
    asm volatile("cp.async.cg.shared.global [%0], [%1], 16;"
                 :: "r"(dst), "l"(src));
}
#define CP_COMMIT() asm volatile("cp.async.commit_group;" ::: "memory")
#define CP_WAIT0()  asm volatile("cp.async.wait_group 0;" ::: "memory")

__device__ __forceinline__ void ldm_x4(uint32_t* r, uint32_t addr) {
    asm volatile("ldmatrix.sync.aligned.m8n8.x4.shared.b16 {%0,%1,%2,%3}, [%4];"
        : "=r"(r[0]), "=r"(r[1]), "=r"(r[2]), "=r"(r[3]) : "r"(addr));
}

__device__ __forceinline__ void mma_bf16(float* c, const uint32_t* a,
                                         const uint32_t* b) {
    asm volatile(
        "mma.sync.aligned.m16n8k16.row.col.f32.bf16.bf16.f32 "
        "{%0,%1,%2,%3}, {%4,%5,%6,%7}, {%8,%9}, {%0,%1,%2,%3};"
        : "+f"(c[0]), "+f"(c[1]), "+f"(c[2]), "+f"(c[3])
        : "r"(a[0]), "r"(a[1]), "r"(a[2]), "r"(a[3]), "r"(b[0]), "r"(b[1]));
}

// bf16 split: hi = bf16(x), lo = bf16(x - hi); packs (e0, e1) pairs.
__device__ __forceinline__ void split_pair(float e0, float e1,
                                           uint32_t& h, uint32_t& l) {
    asm("cvt.rn.bf16x2.f32 %0, %1, %2;" : "=r"(h) : "f"(e1), "f"(e0));
    __nv_bfloat162 hb = *(__nv_bfloat162*)&h;
    float r0 = e0 - __bfloat162float(hb.x);
    float r1 = e1 - __bfloat162float(hb.y);
    asm("cvt.rn.bf16x2.f32 %0, %1, %2;" : "=r"(l) : "f"(r1), "f"(r0));
}

// ============================================================================
// Kernel 0: fp32 -> split-bf16 conversion (memory-bound, runs once per call)
// Each thread converts 8 floats (2x float4) -> 4 hi pairs + 4 lo pairs.
// ============================================================================
__global__ void __launch_bounds__(256)
convert_split(const float* __restrict__ src, __nv_bfloat16* __restrict__ hi,
              __nv_bfloat16* __restrict__ lo)
{
    const int idx = blockIdx.x * 256 + threadIdx.x;
    const float* s = src + (size_t)idx * 8;
    float4 v0 = *(const float4*)(s);
    float4 v1 = *(const float4*)(s + 4);
    uint32_t h[4], l[4];
    split_pair(v0.x, v0.y, h[0], l[0]);
    split_pair(v0.z, v0.w, h[1], l[1]);
    split_pair(v1.x, v1.y, h[2], l[2]);
    split_pair(v1.z, v1.w, h[3], l[3]);
    uint4* hp = (uint4*)(hi + (size_t)idx * 8);
    uint4* lp = (uint4*)(lo + (size_t)idx * 8);
    *hp = make_uint4(h[0], h[1], h[2], h[3]);
    *lp = make_uint4(l[0], l[1], l[2], l[3]);
}

// ============================================================================
// Kernel 1: split-bf16 HMMA GEMM  H[m,d] = sum_k X[m,k]*W[d,k] + b[d]
// CTA 128x128, 8 warps (2x4), warp tile 64x32, K-step 16.
// 2-stage cp.async pipeline, pre-converted bf16 inputs.
// D = Ahi*Bhi + Ahi*Blo + Alo*Bhi (fp32 accumulate).
// ============================================================================
#define SROW 24               // smem row stride in bf16 (48 B, conflict-free)
#define STAGE_B (128 * SROW * 2)   // bytes per tile per stage = 6144

__global__ void __launch_bounds__(256, 1)
gemm_h_mma(const __nv_bfloat16* __restrict__ Xhi,
           const __nv_bfloat16* __restrict__ Xlo,
           const __nv_bfloat16* __restrict__ Whi,
           const __nv_bfloat16* __restrict__ Wlo,
           const float* __restrict__ bias)
{
    __shared__ __nv_bfloat16 sAhi[2][128][SROW];   // 12 KB
    __shared__ __nv_bfloat16 sAlo[2][128][SROW];
    __shared__ __nv_bfloat16 sBhi[2][128][SROW];
    __shared__ __nv_bfloat16 sBlo[2][128][SROW];   // total 48 KB

    const int tid   = threadIdx.x;
    const int wid   = tid >> 5;
    const int lane  = tid & 31;
    const int cta_m = blockIdx.x * 128;
    const int cta_n = blockIdx.y * 128;

    const int wm = (wid & 1) * 64;
    const int wn = (wid >> 1) * 32;

    // cp.async loader mapping: thread -> (row = tid>>1, k-half = tid&1)
    const int lrow  = tid >> 1;
    const int lhalf = (tid & 1) * 8;                 // 8 bf16 = 16 B
    const __nv_bfloat16* srcAhi = Xhi + (size_t)(cta_m + lrow) * DIM + lhalf;
    const __nv_bfloat16* srcAlo = Xlo + (size_t)(cta_m + lrow) * DIM + lhalf;
    const __nv_bfloat16* srcBhi = Whi + (size_t)(cta_n + lrow) * DIM + lhalf;
    const __nv_bfloat16* srcBlo = Wlo + (size_t)(cta_n + lrow) * DIM + lhalf;
    const uint32_t dAhi = smem_u32(&sAhi[0][lrow][lhalf]);
    const uint32_t dAlo = smem_u32(&sAlo[0][lrow][lhalf]);
    const uint32_t dBhi = smem_u32(&sBhi[0][lrow][lhalf]);
    const uint32_t dBlo = smem_u32(&sBlo[0][lrow][lhalf]);

    // ldmatrix addresses for stage 0 (add st*STAGE_B for stage 1)
    uint32_t aAhi[4], aAlo[4];
#pragma unroll
    for (int mt = 0; mt < 4; mt++) {
        int row = wm + mt * 16 + (lane & 15);
        int kh  = (lane >> 4) * 8;
        aAhi[mt] = smem_u32(&sAhi[0][row][kh]);
        aAlo[mt] = smem_u32(&sAlo[0][row][kh]);
    }
    uint32_t bBhi[2], bBlo[2];
#pragma unroll
    for (int nt2 = 0; nt2 < 2; nt2++) {
        int nr = wn + nt2 * 16 + ((lane >> 4) * 8) + (lane & 7);
        int kh = ((lane >> 3) & 1) * 8;
        bBhi[nt2] = smem_u32(&sBhi[0][nr][kh]);
        bBlo[nt2] = smem_u32(&sBlo[0][nr][kh]);
    }

    float acc[4][4][4];
#pragma unroll
    for (int mt = 0; mt < 4; mt++)
#pragma unroll
        for (int nt = 0; nt < 4; nt++)
#pragma unroll
            for (int c = 0; c < 4; c++) acc[mt][nt][c] = 0.f;

    // prologue: stage 0 <- k=0
    cp16(dAhi, srcAhi); cp16(dAlo, srcAlo);
    cp16(dBhi, srcBhi); cp16(dBlo, srcBlo);
    CP_COMMIT();

#pragma unroll 1
    for (int ks = 0; ks < DIM / 16; ks++) {
        CP_WAIT0();
        __syncthreads();

        // issue next-stage loads (overlap with MMA below)
        if (ks + 1 < DIM / 16) {
            const uint32_t so = (uint32_t)(((ks + 1) & 1) * STAGE_B);
            const int ko = (ks + 1) * 16;
            cp16(dAhi + so, srcAhi + ko); cp16(dAlo + so, srcAlo + ko);
            cp16(dBhi + so, srcBhi + ko); cp16(dBlo + so, srcBlo + ko);
        }
        CP_COMMIT();

        const uint32_t st = (uint32_t)((ks & 1) * STAGE_B);

        uint32_t fAhi[4][4], fAlo[4][4];
#pragma unroll
        for (int mt = 0; mt < 4; mt++) {
            ldm_x4(fAhi[mt], aAhi[mt] + st);
            ldm_x4(fAlo[mt], aAlo[mt] + st);
        }
        uint32_t fBhi[4][2], fBlo[4][2];
#pragma unroll
        for (int nt2 = 0; nt2 < 2; nt2++) {
            uint32_t r[4];
            ldm_x4(r, bBhi[nt2] + st);
            fBhi[nt2 * 2][0] = r[0]; fBhi[nt2 * 2][1] = r[1];
            fBhi[nt2 * 2 + 1][0] = r[2]; fBhi[nt2 * 2 + 1][1] = r[3];
            ldm_x4(r, bBlo[nt2] + st);
            fBlo[nt2 * 2][0] = r[0]; fBlo[nt2 * 2][1] = r[1];
            fBlo[nt2 * 2 + 1][0] = r[2]; fBlo[nt2 * 2 + 1][1] = r[3];
        }

#pragma unroll
        for (int mt = 0; mt < 4; mt++)
#pragma unroll
            for (int nt = 0; nt < 4; nt++) {
                mma_bf16(acc[mt][nt], fAhi[mt], fBhi[nt]);
                mma_bf16(acc[mt][nt], fAhi[mt], fBlo[nt]);
                mma_bf16(acc[mt][nt], fAlo[mt], fBhi[nt]);
            }
    }

    // ---- epilogue: +bias, store H ----
    const int gid = lane >> 2;
    const int tig = lane & 3;
#pragma unroll
    for (int nt = 0; nt < 4; nt++) {
        const int col = cta_n + wn + nt * 8 + tig * 2;
        const float2 bv = *(const float2*)(bias + col);
#pragma unroll
        for (int mt = 0; mt < 4; mt++) {
            const int m0 = cta_m + wm + mt * 16 + gid;
            float2 v0 = make_float2(acc[mt][nt][0] + bv.x, acc[mt][nt][1] + bv.y);
            float2 v1 = make_float2(acc[mt][nt][2] + bv.x, acc[mt][nt][3] + bv.y);
            *(float2*)(g_H + (size_t)m0 * DIM + col)       = v0;
            *(float2*)(g_H + (size_t)(m0 + 8) * DIM + col) = v1;
        }
    }
}

// ============================================================================
// Kernel 2: s1[r] = h[r,:]@a1 + att_b ; s2[r] = h[r,:]@a2
// ============================================================================
__global__ void __launch_bounds__(256)
sproj_kernel(const float* __restrict__ a1, const float* __restrict__ a2,
             const float* __restrict__ att_b)
{
    const int row  = blockIdx.x * 8 + (threadIdx.x >> 5);
    const int lane = threadIdx.x & 31;
    const float* hr = g_H + (size_t)row * DIM;

    float d1 = 0.f, d2 = 0.f;
#pragma unroll
    for (int k = lane; k < DIM; k += 32) {
        float hv = hr[k];
        d1 += hv * __ldg(a1 + k);
        d2 += hv * __ldg(a2 + k);
    }
#pragma unroll
    for (int o = 16; o; o >>= 1) {
        d1 += __shfl_xor_sync(0xffffffffu, d1, o);
        d2 += __shfl_xor_sync(0xffffffffu, d2, o);
    }
    if (lane == 0) {
        g_s1[row] = d1 + att_b[0];
        g_s2[row] = d2;
    }
}

// ============================================================================
// Kernel 3: per-node attention + sparse aggregation (passing R2 version).
// ============================================================================
__global__ void __launch_bounds__(256)
attn_agg_kernel(const float* __restrict__ adj, const float* __restrict__ mask,
                float* __restrict__ out)
{
    const int i   = blockIdx.x;
    const int b   = blockIdx.y;
    const int tid = threadIdx.x;
    const int row = b * NNODE + i;

    __shared__ float wbuf[NNODE];
    __shared__ int   jbuf[NNODE];
    __shared__ float sred[4][DIM];
    __shared__ int   s_cnt;
    __shared__ float s_sum;

    const float mi = mask[row];
    float* orow = out + (size_t)row * DIM;
    if (mi == 0.f) {
        orow[tid] = 0.f;
        return;
    }

    if (tid == 0) { s_cnt = 0; s_sum = 0.f; }
    __syncthreads();

    const float* arow = adj + (size_t)row * NNODE;
    const float  s1i  = g_s1[row];
    const float* mrow = mask + b * NNODE;
    const float* s2b  = g_s2 + b * NNODE;
    const int lane = tid & 31;

    float4 av[2], mv[2], sv[2];
#pragma unroll
    for (int u = 0; u < 2; u++) {
        int j0 = tid * 4 + u * 1024;
        av[u] = *(const float4*)(arow + j0);
        mv[u] = *(const float4*)(mrow + j0);
        sv[u] = *(const float4*)(s2b + j0);
    }

    float w[8];
    float psum = 0.f;
#pragma unroll
    for (int u = 0; u < 2; u++) {
        const float* ap = (const float*)&av[u];
        const float* mp = (const float*)&mv[u];
        const float* sp = (const float*)&sv[u];
#pragma unroll
        for (int e = 0; e < 4; e++) {
            float ww = 0.f;
            if (ap[e] != 0.f && mp[e] != 0.f) {
                float lg = s1i + sp[e];
                ww = ap[e] * mp[e] / (1.f + __expf(-lg));
            }
            w[u * 4 + e] = ww;
            psum += ww;
        }
    }

#pragma unroll
    for (int e = 0; e < 8; e++) {
        unsigned bal = __ballot_sync(0xffffffffu, w[e] != 0.f);
        if (bal) {
            int leader = __ffs(bal) - 1;
            int base = 0;
            if (lane == leader) base = atomicAdd(&s_cnt, __popc(bal));
            base = __shfl_sync(0xffffffffu, base, leader);
            if (w[e] != 0.f) {
                int rank = __popc(bal & ((1u << lane) - 1u));
                wbuf[base + rank] = w[e];
                jbuf[base + rank] = tid * 4 + (e >> 2) * 1024 + (e & 3);
            }
        }
    }

#pragma unroll
    for (int o = 16; o; o >>= 1) psum += __shfl_xor_sync(0xffffffffu, psum, o);
    if (lane == 0) atomicAdd(&s_sum, psum);
    __syncthreads();

    const int n   = s_cnt;
    const float inv = 1.f / (s_sum + 1e-8f);
    const float* Hb = g_H + (size_t)b * NNODE * DIM;

    const int g  = tid >> 6;
    const int c4 = (tid & 63) * 4;

    float4 acc = make_float4(0.f, 0.f, 0.f, 0.f);
    int k = g;
    for (; k + 4 < n; k += 8) {
        int   ja = jbuf[k],   jc = jbuf[k + 4];
        float wa = wbuf[k],   wc = wbuf[k + 4];
        float4 ha = *(const float4*)(Hb + (size_t)ja * DIM + c4);
        float4 hc = *(const float4*)(Hb + (size_t)jc * DIM + c4);
        acc.x += wa * ha.x + wc * hc.x;
        acc.y += wa * ha.y + wc * hc.y;
        acc.z += wa * ha.z + wc * hc.z;
        acc.w += wa * ha.w + wc * hc.w;
    }
    if (k < n) {
        int   ja = jbuf[k];
        float wa = wbuf[k];
        float4 ha = *(const float4*)(Hb + (size_t)ja * DIM + c4);
        acc.x += wa * ha.x; acc.y += wa * ha.y;
        acc.z += wa * ha.z; acc.w += wa * ha.w;
    }

    *(float4*)&sred[g][c4] = acc;
    __syncthreads();

    float r = sred[0][tid] + sred[1][tid] + sred[2][tid] + sred[3][tid];
    orow[tid] = r * inv;
}

// ============================================================================
// Launch
// ============================================================================
extern "C" void kernel_launch(void* const* d_in, const int* in_sizes, int n_in,
                              void* d_out, int out_size)
{
    const float* x     = (const float*)d_in[0];
    const float* adj   = (const float*)d_in[1];
    const float* mask  = (const float*)d_in[2];
    const float* W     = (const float*)d_in[3];
    const float* bias  = (const float*)d_in[4];
    const float* a1    = (const float*)d_in[5];
    const float* a2    = (const float*)d_in[6];
    const float* att_b = (const float*)d_in[7];
    float* out = (float*)d_out;

    __nv_bfloat16 *xhi, *xlo, *whi, *wlo;
    cudaGetSymbolAddress((void**)&xhi, g_Xhi);
    cudaGetSymbolAddress((void**)&xlo, g_Xlo);
    cudaGetSymbolAddress((void**)&whi, g_Whi);
    cudaGetSymbolAddress((void**)&wlo, g_Wlo);

    convert_split<<<(MROWS * DIM) / (256 * 8), 256>>>(x, xhi, xlo);
    convert_split<<<(DIM * DIM) / (256 * 8), 256>>>(W, whi, wlo);

    dim3 g1(MROWS / 128, DIM / 128);      // (128, 2)
    gemm_h_mma<<<g1, 256>>>(xhi, xlo, whi, wlo, bias);

    sproj_kernel<<<MROWS / 8, 256>>>(a1, a2, att_b);

    dim3 g3(NNODE, BATCH);                // (2048, 8)
    attn_agg_kernel<<<g3, 256>>>(adj, mask, out);
}